// round 7
// baseline (speedup 1.0000x reference)
#include <cuda_runtime.h>
#include <cuda_bf16.h>
#include <math.h>
#include <stdint.h>

#define DIM   2048
#define SEQ   2048
#define NH    32
#define KVH   8
#define HD    64
#define NE    8
#define FF    7168
#define CAP   2048
#define QKVN  3072

// ---------------- scratch (device globals) ------------------------------------
static __device__ float g_hn  [SEQ * DIM];
static __device__ float g_wqkv[DIM * QKVN];
static __device__ float g_qkv [SEQ * QKVN];
static __device__ float g_attn[SEQ * NH * HD];
static __device__ float g_h2  [SEQ * DIM];
static __device__ float g_hn2 [SEQ * DIM];
static __device__ float g_xe  [(size_t)NE * CAP * DIM];
static __device__ float g_gate[(size_t)NE * CAP * FF];
static __device__ float g_up  [(size_t)NE * CAP * FF];
static __device__ float g_down[(size_t)NE * CAP * DIM];
static __device__ int   g_cnt [NE];
static __device__ int   g_eid [SEQ * 2];
static __device__ int   g_slot[SEQ * 2];
static __device__ float g_w   [SEQ * 2];

// ---------------- helpers ------------------------------------------------------
__device__ __forceinline__ uint32_t pack2(float x0, float x1) {
    uint32_t u;
    asm("cvt.rn.bf16x2.f32 %0, %1, %2;" : "=r"(u) : "f"(x1), "f"(x0));
    return u;
}
__device__ __forceinline__ void unpack2(uint32_t u, float& f0, float& f1) {
    __nv_bfloat162 t = *reinterpret_cast<__nv_bfloat162*>(&u);
    f0 = __bfloat162float(t.x);
    f1 = __bfloat162float(t.y);
}
__device__ __forceinline__ void mma_bf16(float* d, const uint32_t* a, const uint32_t* b) {
    asm volatile(
        "mma.sync.aligned.m16n8k16.row.col.f32.bf16.bf16.f32 "
        "{%0,%1,%2,%3}, {%4,%5,%6,%7}, {%8,%9}, {%0,%1,%2,%3};"
        : "+f"(d[0]), "+f"(d[1]), "+f"(d[2]), "+f"(d[3])
        : "r"(a[0]), "r"(a[1]), "r"(a[2]), "r"(a[3]), "r"(b[0]), "r"(b[1]));
}

// ------------- 3xBF16 GEMM: 128x128x32 tile, 512 threads, 4x4 warps -----------
#define BM 128
#define BN 128
#define BK 32
#define A_STRIDE 20
#define B_STRIDE 136
#define A_TILE_U32 (BM * A_STRIDE)   // 2560
#define B_TILE_U32 (16 * B_STRIDE)   // 2176
#define STAGE_U32 (2 * A_TILE_U32 + 2 * B_TILE_U32)   // 9472
#define GSMEM_BYTES (2 * STAGE_U32 * 4)               // 75776

__global__ void __launch_bounds__(512)
gemm_tc(const float* __restrict__ A, const float* __restrict__ B, float* __restrict__ C,
        int M, int N, int K, const int* __restrict__ cnt,
        size_t sA, size_t sB, size_t sC) {
    int e = blockIdx.z;
    int m = cnt ? cnt[e] : M;
    int m0 = blockIdx.y * BM;
    if (m0 >= m) return;
    int n0 = blockIdx.x * BN;

    extern __shared__ uint32_t smu[];
    uint32_t* bufs[2] = { smu, smu + STAGE_U32 };

    const float* Ab = A + sA * (size_t)e;
    const float* Bb = B + sB * (size_t)e;
    float*       Cb = C + sC * (size_t)e;

    int tid = threadIdx.x;
    int warp = tid >> 5, lane = tid & 31;
    int wm = warp >> 2, wn = warp & 3;        // 4 x 4 warp grid, warp tile 32x32
    int g = lane >> 2, c = lane & 3;

    // A copy role: 8 k-consecutive floats per thread (4 threads per row)
    int a_row = tid >> 2, a_q = tid & 3;
    int a_src = m0 + a_row < m ? m0 + a_row : m - 1;
    const float* Aptr = Ab + (size_t)a_src * K + a_q * 8;
    // B copy role: 4 n-floats from two adjacent k-rows per thread
    int b_kp = tid >> 5, b_nc = (tid & 31) * 4;
    const float* Bptr = Bb + (size_t)(2 * b_kp) * N + n0 + b_nc;

    float acc[2][4][4];
    #pragma unroll
    for (int i = 0; i < 2; i++)
        #pragma unroll
        for (int j = 0; j < 4; j++)
            #pragma unroll
            for (int q = 0; q < 4; q++) acc[i][j][q] = 0.f;

    float aR[8], bR[8];

    auto load_regs = [&](int kb) {
        ((float4*)aR)[0] = *(const float4*)(Aptr + kb);
        ((float4*)aR)[1] = *(const float4*)(Aptr + kb + 4);
        const float* bp2 = Bptr + (size_t)kb * N;
        ((float4*)bR)[0] = *(const float4*)(bp2);
        ((float4*)bR)[1] = *(const float4*)(bp2 + N);
    };
    auto convert_store = [&](uint32_t* buf) {
        uint32_t* Ah = buf;
        uint32_t* Al = buf + A_TILE_U32;
        uint32_t* Bh = buf + 2 * A_TILE_U32;
        uint32_t* Bl = Bh + B_TILE_U32;
        {
            uint32_t hh[4], ll[4];
            #pragma unroll
            for (int p = 0; p < 4; p++) {
                float x0 = aR[2 * p], x1 = aR[2 * p + 1];
                uint32_t hv = pack2(x0, x1);
                float f0, f1; unpack2(hv, f0, f1);
                hh[p] = hv;
                ll[p] = pack2(x0 - f0, x1 - f1);
            }
            int idx = a_row * A_STRIDE + a_q * 4;
            *(uint4*)&Ah[idx] = *(uint4*)&hh[0];
            *(uint4*)&Al[idx] = *(uint4*)&ll[0];
        }
        {
            uint32_t hh[4], ll[4];
            #pragma unroll
            for (int j = 0; j < 4; j++) {
                float x0 = bR[j], x1 = bR[4 + j];   // k even, k odd
                uint32_t hv = pack2(x0, x1);
                float f0, f1; unpack2(hv, f0, f1);
                hh[j] = hv;
                ll[j] = pack2(x0 - f0, x1 - f1);
            }
            int idx = b_kp * B_STRIDE + b_nc;
            *(uint4*)&Bh[idx] = *(uint4*)&hh[0];
            *(uint4*)&Bl[idx] = *(uint4*)&ll[0];
        }
    };

    int nst = K / BK;
    load_regs(0);
    convert_store(bufs[0]);

    for (int s = 0; s < nst; s++) {
        uint32_t* buf = bufs[s & 1];
        uint32_t* Ah = buf;
        uint32_t* Al = buf + A_TILE_U32;
        uint32_t* Bh = buf + 2 * A_TILE_U32;
        uint32_t* Bl = Bh + B_TILE_U32;
        __syncthreads();
        if (s + 1 < nst) load_regs((s + 1) * BK);

        #pragma unroll
        for (int ks = 0; ks < 2; ks++) {
            uint32_t bh[4][2], bl[4][2];
            #pragma unroll
            for (int nt = 0; nt < 4; nt++) {
                int n = wn * 32 + nt * 8 + g;
                int k0 = (ks * 8 + c) * B_STRIDE + n;
                int k1 = (ks * 8 + c + 4) * B_STRIDE + n;
                bh[nt][0] = Bh[k0]; bh[nt][1] = Bh[k1];
                bl[nt][0] = Bl[k0]; bl[nt][1] = Bl[k1];
            }
            #pragma unroll
            for (int mt = 0; mt < 2; mt++) {
                int row = wm * 32 + mt * 16 + g;
                int i0 = row * A_STRIDE + ks * 8 + c;
                int i1 = (row + 8) * A_STRIDE + ks * 8 + c;
                uint32_t ah[4], al[4];
                ah[0] = Ah[i0]; ah[1] = Ah[i1]; ah[2] = Ah[i0 + 4]; ah[3] = Ah[i1 + 4];
                al[0] = Al[i0]; al[1] = Al[i1]; al[2] = Al[i0 + 4]; al[3] = Al[i1 + 4];
                #pragma unroll
                for (int nt = 0; nt < 4; nt++) {
                    mma_bf16(acc[mt][nt], ah, bh[nt]);
                    mma_bf16(acc[mt][nt], ah, bl[nt]);
                    mma_bf16(acc[mt][nt], al, bh[nt]);
                }
            }
        }
        if (s + 1 < nst) convert_store(bufs[(s + 1) & 1]);
    }

    #pragma unroll
    for (int mt = 0; mt < 2; mt++) {
        int r = m0 + wm * 32 + mt * 16 + g;
        #pragma unroll
        for (int nt = 0; nt < 4; nt++) {
            int col = n0 + wn * 32 + nt * 8 + c * 2;
            if (r < m)
                *(float2*)&Cb[(size_t)r * N + col] = make_float2(acc[mt][nt][0], acc[mt][nt][1]);
            if (r + 8 < m)
                *(float2*)&Cb[(size_t)(r + 8) * N + col] = make_float2(acc[mt][nt][2], acc[mt][nt][3]);
        }
    }
}

// ---------------- tensor-core flash attention (3xbf16 both GEMMs) --------------
#define KV_STR 36

__global__ void __launch_bounds__(128)
attn_tc(const float* __restrict__ qkv, float* __restrict__ o) {
    __shared__ uint32_t Kh[64 * KV_STR], Kl[64 * KV_STR];
    __shared__ uint32_t Vh[64 * KV_STR], Vl[64 * KV_STR];
    int qt = blockIdx.x, h = blockIdx.y;
    int tid = threadIdx.x, warp = tid >> 5, lane = tid & 31;
    int g = lane >> 2, c = lane & 3;
    int kvh = h >> 2;

    uint32_t Qh[4][4], Ql[4][4];
    {
        int r0 = qt * 64 + warp * 16 + g;
        const float* q0 = qkv + (size_t)r0 * QKVN + h * HD;
        const float* q1 = q0 + 8 * QKVN;
        #pragma unroll
        for (int ks = 0; ks < 4; ks++) {
            #pragma unroll
            for (int half = 0; half < 2; half++) {
                int d = ks * 16 + half * 8 + 2 * c;
                float x0 = q0[d] * 0.125f, x1 = q0[d + 1] * 0.125f;
                float y0 = q1[d] * 0.125f, y1 = q1[d + 1] * 0.125f;
                uint32_t hx = pack2(x0, x1), hy = pack2(y0, y1);
                float fx0, fx1, fy0, fy1;
                unpack2(hx, fx0, fx1);
                unpack2(hy, fy0, fy1);
                Qh[ks][half * 2]     = hx;
                Qh[ks][half * 2 + 1] = hy;
                Ql[ks][half * 2]     = pack2(x0 - fx0, x1 - fx1);
                Ql[ks][half * 2 + 1] = pack2(y0 - fy0, y1 - fy1);
            }
        }
    }

    float acc[8][4];
    #pragma unroll
    for (int nt = 0; nt < 8; nt++)
        #pragma unroll
        for (int q = 0; q < 4; q++) acc[nt][q] = 0.f;
    float m0 = -1e30f, m1 = -1e30f, l0 = 0.f, l1 = 0.f;

    for (int kt = 0; kt <= qt; kt++) {
        {
            int tok = tid >> 1, half = tid & 1;
            const float* kp = qkv + (size_t)(kt * 64 + tok) * QKVN + 2048 + kvh * HD + half * 32;
            float v[32];
            #pragma unroll
            for (int j = 0; j < 8; j++) ((float4*)v)[j] = ((const float4*)kp)[j];
            int base = tok * KV_STR + half * 16;
            #pragma unroll
            for (int j = 0; j < 16; j++) {
                uint32_t hv = pack2(v[2 * j], v[2 * j + 1]);
                float f0, f1; unpack2(hv, f0, f1);
                Kh[base + j] = hv;
                Kl[base + j] = pack2(v[2 * j] - f0, v[2 * j + 1] - f1);
            }
        }
        {
            const float* vp0 = qkv + (size_t)(kt * 64 + 2 * lane) * QKVN + 2560 + kvh * HD + warp * 16;
            const float* vp1 = vp0 + QKVN;
            float va[16], vb[16];
            #pragma unroll
            for (int j = 0; j < 4; j++) {
                ((float4*)va)[j] = ((const float4*)vp0)[j];
                ((float4*)vb)[j] = ((const float4*)vp1)[j];
            }
            #pragma unroll
            for (int i = 0; i < 16; i++) {
                uint32_t hv = pack2(va[i], vb[i]);
                float f0, f1; unpack2(hv, f0, f1);
                int idx = (warp * 16 + i) * KV_STR + lane;
                Vh[idx] = hv;
                Vl[idx] = pack2(va[i] - f0, vb[i] - f1);
            }
        }
        __syncthreads();

        float s[8][4];
        #pragma unroll
        for (int nt = 0; nt < 8; nt++)
            #pragma unroll
            for (int q = 0; q < 4; q++) s[nt][q] = 0.f;
        #pragma unroll
        for (int ks = 0; ks < 4; ks++) {
            #pragma unroll
            for (int nt = 0; nt < 8; nt++) {
                int idx = (nt * 8 + g) * KV_STR + ks * 8 + c;
                uint32_t bh[2] = { Kh[idx], Kh[idx + 4] };
                uint32_t bl[2] = { Kl[idx], Kl[idx + 4] };
                mma_bf16(s[nt], Qh[ks], bh);
                mma_bf16(s[nt], Ql[ks], bh);
                mma_bf16(s[nt], Qh[ks], bl);
            }
        }
        if (kt == qt) {
            int row0 = warp * 16 + g, row1 = row0 + 8;
            #pragma unroll
            for (int nt = 0; nt < 8; nt++) {
                int col = nt * 8 + 2 * c;
                if (col > row0)     s[nt][0] = -1e30f;
                if (col + 1 > row0) s[nt][1] = -1e30f;
                if (col > row1)     s[nt][2] = -1e30f;
                if (col + 1 > row1) s[nt][3] = -1e30f;
            }
        }
        float mx0 = -1e30f, mx1 = -1e30f;
        #pragma unroll
        for (int nt = 0; nt < 8; nt++) {
            mx0 = fmaxf(mx0, fmaxf(s[nt][0], s[nt][1]));
            mx1 = fmaxf(mx1, fmaxf(s[nt][2], s[nt][3]));
        }
        mx0 = fmaxf(mx0, __shfl_xor_sync(0xffffffffu, mx0, 1));
        mx0 = fmaxf(mx0, __shfl_xor_sync(0xffffffffu, mx0, 2));
        mx1 = fmaxf(mx1, __shfl_xor_sync(0xffffffffu, mx1, 1));
        mx1 = fmaxf(mx1, __shfl_xor_sync(0xffffffffu, mx1, 2));
        float mn0 = fmaxf(m0, mx0), mn1 = fmaxf(m1, mx1);
        float sc0 = expf(m0 - mn0), sc1 = expf(m1 - mn1);
        m0 = mn0; m1 = mn1;
        l0 *= sc0; l1 *= sc1;
        #pragma unroll
        for (int nt = 0; nt < 8; nt++) {
            acc[nt][0] *= sc0; acc[nt][1] *= sc0;
            acc[nt][2] *= sc1; acc[nt][3] *= sc1;
        }
        #pragma unroll
        for (int nt = 0; nt < 8; nt++) {
            s[nt][0] = expf(s[nt][0] - m0);
            s[nt][1] = expf(s[nt][1] - m0);
            s[nt][2] = expf(s[nt][2] - m1);
            s[nt][3] = expf(s[nt][3] - m1);
            l0 += s[nt][0] + s[nt][1];
            l1 += s[nt][2] + s[nt][3];
        }
        uint32_t Ph[4][4], Pl[4][4];
        #pragma unroll
        for (int j = 0; j < 4; j++) {
            #pragma unroll
            for (int q = 0; q < 4; q++) {
                int nt = 2 * j + (q >> 1);
                float x0 = s[nt][(q & 1) * 2], x1 = s[nt][(q & 1) * 2 + 1];
                uint32_t hv = pack2(x0, x1);
                float f0, f1; unpack2(hv, f0, f1);
                Ph[j][q] = hv;
                Pl[j][q] = pack2(x0 - f0, x1 - f1);
            }
        }
        #pragma unroll
        for (int j = 0; j < 4; j++) {
            #pragma unroll
            for (int nt = 0; nt < 8; nt++) {
                int idx = (nt * 8 + g) * KV_STR + j * 8 + c;
                uint32_t bh[2] = { Vh[idx], Vh[idx + 4] };
                uint32_t bl[2] = { Vl[idx], Vl[idx + 4] };
                mma_bf16(acc[nt], Ph[j], bh);
                mma_bf16(acc[nt], Pl[j], bh);
                mma_bf16(acc[nt], Ph[j], bl);
            }
        }
        __syncthreads();
    }

    l0 += __shfl_xor_sync(0xffffffffu, l0, 1);
    l0 += __shfl_xor_sync(0xffffffffu, l0, 2);
    l1 += __shfl_xor_sync(0xffffffffu, l1, 1);
    l1 += __shfl_xor_sync(0xffffffffu, l1, 2);
    float inv0 = 1.f / l0, inv1 = 1.f / l1;
    int r0 = qt * 64 + warp * 16 + g;
    float* op0 = o + (size_t)r0 * (NH * HD) + h * HD;
    float* op1 = op0 + 8 * (NH * HD);
    #pragma unroll
    for (int nt = 0; nt < 8; nt++) {
        *(float2*)&op0[nt * 8 + 2 * c] = make_float2(acc[nt][0] * inv0, acc[nt][1] * inv0);
        *(float2*)&op1[nt * 8 + 2 * c] = make_float2(acc[nt][2] * inv1, acc[nt][3] * inv1);
    }
}

// ---------------- small kernels ------------------------------------------------
__global__ void zero_cnt_kernel() {
    if (threadIdx.x < NE) g_cnt[threadIdx.x] = 0;
}

__global__ void pack_qkv_kernel(const float* __restrict__ Wq, const float* __restrict__ Wk,
                                const float* __restrict__ Wv) {
    int idx = blockIdx.x * blockDim.x + threadIdx.x;
    if (idx >= DIM * QKVN) return;
    int k = idx / QKVN, n = idx % QKVN;
    float v;
    if (n < 2048)      v = Wq[k * 2048 + n];
    else if (n < 2560) v = Wk[k * 512 + (n - 2048)];
    else               v = Wv[k * 512 + (n - 2560)];
    g_wqkv[idx] = v;
}

__global__ void rmsnorm_kernel(const float* __restrict__ x,
                               const float* __restrict__ w,
                               float* __restrict__ o) {
    int row = blockIdx.x;
    const float* xr = x + (size_t)row * DIM;
    float s = 0.f;
    for (int i = threadIdx.x; i < DIM; i += blockDim.x) {
        float v = xr[i];
        s += v * v;
    }
    __shared__ float red[32];
    int lane = threadIdx.x & 31, wid = threadIdx.x >> 5;
    #pragma unroll
    for (int off = 16; off; off >>= 1) s += __shfl_down_sync(0xffffffffu, s, off);
    if (lane == 0) red[wid] = s;
    __syncthreads();
    if (wid == 0) {
        float t = (lane < (blockDim.x >> 5)) ? red[lane] : 0.f;
        #pragma unroll
        for (int off = 16; off; off >>= 1) t += __shfl_down_sync(0xffffffffu, t, off);
        if (lane == 0) red[0] = t;
    }
    __syncthreads();
    float scale = rsqrtf(red[0] / (float)DIM + 1e-5f);
    float* orow = o + (size_t)row * DIM;
    for (int i = threadIdx.x; i < DIM; i += blockDim.x)
        orow[i] = xr[i] * scale * w[i];
}

__global__ void add_kernel(const float* __restrict__ a, const float* __restrict__ b,
                           float* __restrict__ o, int n) {
    int i = blockIdx.x * blockDim.x + threadIdx.x;
    if (i < n) o[i] = a[i] + b[i];
}

__global__ void rope_kernel(float* __restrict__ x, const int* __restrict__ pos,
                            int heads, int stride, int off) {
    int idx = blockIdx.x * blockDim.x + threadIdx.x;
    int total = SEQ * heads * (HD / 2);
    if (idx >= total) return;
    int d = idx & 31;
    int t = idx >> 5;
    int h = t % heads;
    int s = t / heads;
    double invd = pow(1.0e6, -(double)d / 32.0);
    float ang = (float)((double)pos[s] * invd);
    float cs, sn;
    sincosf(ang, &sn, &cs);
    float* p = x + (size_t)s * stride + off + h * HD;
    float x1 = p[d], x2 = p[d + 32];
    p[d]      = x1 * cs - x2 * sn;
    p[d + 32] = x2 * cs + x1 * sn;
}

__global__ void router_kernel(const float* __restrict__ x, const float* __restrict__ Wr) {
    int warp = (blockIdx.x * blockDim.x + threadIdx.x) >> 5;
    int lane = threadIdx.x & 31;
    if (warp >= SEQ) return;
    const float* xr = x + (size_t)warp * DIM;
    float acc[NE];
    #pragma unroll
    for (int e = 0; e < NE; e++) acc[e] = 0.f;
    for (int d = lane; d < DIM; d += 32) {
        float xv = xr[d];
        #pragma unroll
        for (int e = 0; e < NE; e++) acc[e] += xv * Wr[d * NE + e];
    }
    #pragma unroll
    for (int e = 0; e < NE; e++)
        #pragma unroll
        for (int off = 16; off; off >>= 1)
            acc[e] += __shfl_down_sync(0xffffffffu, acc[e], off);
    if (lane == 0) {
        int i1 = 0;
        #pragma unroll
        for (int e = 1; e < NE; e++) if (acc[e] > acc[i1]) i1 = e;
        int i2 = (i1 == 0) ? 1 : 0;
        #pragma unroll
        for (int e = 0; e < NE; e++) if (e != i1 && acc[e] > acc[i2]) i2 = e;
        float w1 = 1.f / (1.f + expf(acc[i2] - acc[i1]));
        int s0 = atomicAdd(&g_cnt[i1], 1);
        int s1 = atomicAdd(&g_cnt[i2], 1);
        g_eid[warp * 2]  = i1; g_eid[warp * 2 + 1]  = i2;
        g_slot[warp * 2] = s0; g_slot[warp * 2 + 1] = s1;
        g_w[warp * 2]    = w1; g_w[warp * 2 + 1]    = 1.f - w1;
    }
}

__global__ void gather_kernel(const float* __restrict__ x) {
    int pair = blockIdx.x;
    int n = pair >> 1, j = pair & 1;
    int e = g_eid[n * 2 + j], s = g_slot[n * 2 + j];
    const float4* src = (const float4*)(x + (size_t)n * DIM);
    float4* dst = (float4*)(g_xe + ((size_t)e * CAP + s) * DIM);
    for (int i = threadIdx.x; i < DIM / 4; i += blockDim.x) dst[i] = src[i];
}

__global__ void silu_mul_kernel() {
    int e = blockIdx.z;
    int r = blockIdx.y;
    if (r >= g_cnt[e]) return;
    size_t base = ((size_t)e * CAP + r) * FF;
    int c = blockIdx.x * blockDim.x + threadIdx.x;
    float g = g_gate[base + c];
    float u = g_up[base + c];
    g_gate[base + c] = (g / (1.f + expf(-g))) * u;
}

__global__ void combine_kernel(float* __restrict__ out) {
    int idx = blockIdx.x * blockDim.x + threadIdx.x;
    if (idx >= SEQ * DIM) return;
    int n = idx >> 11;
    int d = idx & (DIM - 1);
    int e0 = g_eid[n * 2],  e1 = g_eid[n * 2 + 1];
    int s0 = g_slot[n * 2], s1 = g_slot[n * 2 + 1];
    out[idx] = g_h2[idx]
             + g_w[n * 2]     * g_down[((size_t)e0 * CAP + s0) * DIM + d]
             + g_w[n * 2 + 1] * g_down[((size_t)e1 * CAP + s1) * DIM + d];
}

// ---------------- launch -------------------------------------------------------
extern "C" void kernel_launch(void* const* d_in, const int* in_sizes, int n_in,
                              void* d_out, int out_size) {
    const float* hidden = (const float*)d_in[0];
    const int*   pos    = (const int*)  d_in[1];
    const float* ln1    = (const float*)d_in[2];
    const float* Wq     = (const float*)d_in[3];
    const float* Wk     = (const float*)d_in[4];
    const float* Wv     = (const float*)d_in[5];
    const float* Wo     = (const float*)d_in[6];
    const float* ln2    = (const float*)d_in[7];
    const float* Wr     = (const float*)d_in[8];
    const float* W1     = (const float*)d_in[9];
    const float* W3     = (const float*)d_in[10];
    const float* W2     = (const float*)d_in[11];
    float* out = (float*)d_out;

    float *p_hn, *p_wqkv, *p_qkv, *p_attn, *p_h2, *p_hn2, *p_xe, *p_gate, *p_up, *p_down;
    cudaGetSymbolAddress((void**)&p_hn,   g_hn);
    cudaGetSymbolAddress((void**)&p_wqkv, g_wqkv);
    cudaGetSymbolAddress((void**)&p_qkv,  g_qkv);
    cudaGetSymbolAddress((void**)&p_attn, g_attn);
    cudaGetSymbolAddress((void**)&p_h2,   g_h2);
    cudaGetSymbolAddress((void**)&p_hn2,  g_hn2);
    cudaGetSymbolAddress((void**)&p_xe,   g_xe);
    cudaGetSymbolAddress((void**)&p_gate, g_gate);
    cudaGetSymbolAddress((void**)&p_up,   g_up);
    cudaGetSymbolAddress((void**)&p_down, g_down);
    int* p_cnt;
    cudaGetSymbolAddress((void**)&p_cnt, g_cnt);

    static int smem_set = 0;
    if (!smem_set) {
        cudaFuncSetAttribute(gemm_tc, cudaFuncAttributeMaxDynamicSharedMemorySize, GSMEM_BYTES);
        smem_set = 1;
    }

    zero_cnt_kernel<<<1, 32>>>();
    rmsnorm_kernel<<<SEQ, 256>>>(hidden, ln1, p_hn);
    pack_qkv_kernel<<<(DIM * QKVN + 255) / 256, 256>>>(Wq, Wk, Wv);

    // QKV projection: [2048,2048] @ [2048,3072]
    gemm_tc<<<dim3(QKVN / BN, SEQ / BM, 1), 512, GSMEM_BYTES>>>(
        p_hn, p_wqkv, p_qkv, SEQ, QKVN, DIM, 0, 0, 0, 0);

    rope_kernel<<<(SEQ * NH * (HD / 2) + 255) / 256, 256>>>(p_qkv, pos, NH, QKVN, 0);
    rope_kernel<<<(SEQ * KVH * (HD / 2) + 255) / 256, 256>>>(p_qkv, pos, KVH, QKVN, 2048);

    attn_tc<<<dim3(SEQ / 64, NH, 1), 128>>>(p_qkv, p_attn);

    // O projection + residual
    gemm_tc<<<dim3(DIM / BN, SEQ / BM, 1), 512, GSMEM_BYTES>>>(
        p_attn, Wo, p_hn, SEQ, DIM, NH * HD, 0, 0, 0, 0);
    add_kernel<<<(SEQ * DIM + 255) / 256, 256>>>(hidden, p_hn, p_h2, SEQ * DIM);

    rmsnorm_kernel<<<SEQ, 256>>>(p_h2, ln2, p_hn2);
    router_kernel<<<(SEQ * 32 + 255) / 256, 256>>>(p_hn2, Wr);
    gather_kernel<<<SEQ * 2, 256>>>(p_hn2);

    // expert GEMMs (device-count early exit)
    gemm_tc<<<dim3(FF / BN, CAP / BM, NE), 512, GSMEM_BYTES>>>(
        p_xe, W1, p_gate, CAP, FF, DIM, p_cnt,
        (size_t)CAP * DIM, (size_t)DIM * FF, (size_t)CAP * FF);
    gemm_tc<<<dim3(FF / BN, CAP / BM, NE), 512, GSMEM_BYTES>>>(
        p_xe, W3, p_up, CAP, FF, DIM, p_cnt,
        (size_t)CAP * DIM, (size_t)DIM * FF, (size_t)CAP * FF);
    silu_mul_kernel<<<dim3(FF / 256, CAP, NE), 256>>>();
    gemm_tc<<<dim3(DIM / BN, CAP / BM, NE), 512, GSMEM_BYTES>>>(
        p_gate, W2, p_down, CAP, DIM, FF, p_cnt,
        (size_t)CAP * FF, (size_t)FF * DIM, (size_t)CAP * DIM);

    combine_kernel<<<(SEQ * DIM + 255) / 256, 256>>>(out);
}

// round 10
// speedup vs baseline: 1.0081x; 1.0081x over previous
#include <cuda_runtime.h>
#include <cuda_bf16.h>
#include <math.h>
#include <stdint.h>

#define DIM   2048
#define SEQ   2048
#define NH    32
#define KVH   8
#define HD    64
#define NE    8
#define FF    7168
#define CAP   2048
#define QKVN  3072

// ---------------- scratch (device globals) ------------------------------------
static __device__ float g_hn  [SEQ * DIM];
static __device__ float g_wqkv[DIM * QKVN];
static __device__ float g_qkv [SEQ * QKVN];
static __device__ float g_attn[SEQ * NH * HD];
static __device__ float g_h2  [SEQ * DIM];
static __device__ float g_hn2 [SEQ * DIM];
static __device__ float g_xe  [(size_t)NE * CAP * DIM];
static __device__ float g_gate[(size_t)NE * CAP * FF];
static __device__ float g_up  [(size_t)NE * CAP * FF];
static __device__ float g_down[(size_t)NE * CAP * DIM];
static __device__ int   g_cnt [NE];
static __device__ int   g_eid [SEQ * 2];
static __device__ int   g_slot[SEQ * 2];
static __device__ float g_w   [SEQ * 2];

// ---------------- helpers ------------------------------------------------------
__device__ __forceinline__ uint32_t pack2(float x0, float x1) {
    uint32_t u;
    asm("cvt.rn.bf16x2.f32 %0, %1, %2;" : "=r"(u) : "f"(x1), "f"(x0));
    return u;
}
__device__ __forceinline__ void unpack2(uint32_t u, float& f0, float& f1) {
    __nv_bfloat162 t = *reinterpret_cast<__nv_bfloat162*>(&u);
    f0 = __bfloat162float(t.x);
    f1 = __bfloat162float(t.y);
}
__device__ __forceinline__ void mma_bf16(float* d, const uint32_t* a, const uint32_t* b) {
    asm volatile(
        "mma.sync.aligned.m16n8k16.row.col.f32.bf16.bf16.f32 "
        "{%0,%1,%2,%3}, {%4,%5,%6,%7}, {%8,%9}, {%0,%1,%2,%3};"
        : "+f"(d[0]), "+f"(d[1]), "+f"(d[2]), "+f"(d[3])
        : "r"(a[0]), "r"(a[1]), "r"(a[2]), "r"(a[3]), "r"(b[0]), "r"(b[1]));
}

// ------- 3xBF16 GEMM: 128x64x32 tile, 256 threads, 2 CTAs/SM -------------------
#define BM 128
#define BN 64
#define BK 32
#define A_STRIDE 20                  // u32 per A row (16 kpairs + 4 pad); 20%32 conflict-free
#define B_STRIDE 72                  // u32 per kpair row (64 n + 8 pad); 72%32==8 conflict-free
#define A_TILE_U32 (BM * A_STRIDE)   // 2560
#define B_TILE_U32 (16 * B_STRIDE)   // 1152
#define STAGE_U32 (2 * A_TILE_U32 + 2 * B_TILE_U32)   // 7424
#define GSMEM_BYTES (2 * STAGE_U32 * 4)               // 59392

__global__ void __launch_bounds__(256, 2)
gemm_tc(const float* __restrict__ A, const float* __restrict__ B, float* __restrict__ C,
        int M, int N, int K, const int* __restrict__ cnt,
        size_t sA, size_t sB, size_t sC) {
    int e = blockIdx.z;
    int m = cnt ? cnt[e] : M;
    int m0 = blockIdx.y * BM;
    if (m0 >= m) return;
    int n0 = blockIdx.x * BN;

    extern __shared__ uint32_t smu[];
    uint32_t* bufs[2] = { smu, smu + STAGE_U32 };

    const float* Ab = A + sA * (size_t)e;
    const float* Bb = B + sB * (size_t)e;
    float*       Cb = C + sC * (size_t)e;

    int tid = threadIdx.x;
    int warp = tid >> 5, lane = tid & 31;
    int wm = warp >> 1, wn = warp & 1;       // 4 x 2 warp grid, warp tile 32x32
    int g = lane >> 2, c = lane & 3;

    // A copy role: 16 k-consecutive floats per thread (2 threads per row)
    int a_row = tid >> 1, a_half = tid & 1;
    int a_src = m0 + a_row < m ? m0 + a_row : m - 1;
    const float* Aptr = Ab + (size_t)a_src * K + a_half * 16;
    // B copy role: 4 n-floats from two adjacent k-rows per thread
    int b_kp = tid >> 4, b_nc = (tid & 15) * 4;
    const float* Bptr = Bb + (size_t)(2 * b_kp) * N + n0 + b_nc;

    float acc[2][4][4];
    #pragma unroll
    for (int i = 0; i < 2; i++)
        #pragma unroll
        for (int j = 0; j < 4; j++)
            #pragma unroll
            for (int q = 0; q < 4; q++) acc[i][j][q] = 0.f;

    float aR[16], bR[8];

    auto load_regs = [&](int kb) {
        #pragma unroll
        for (int j = 0; j < 4; j++) ((float4*)aR)[j] = *(const float4*)(Aptr + kb + j * 4);
        const float* bp2 = Bptr + (size_t)kb * N;
        ((float4*)bR)[0] = *(const float4*)(bp2);
        ((float4*)bR)[1] = *(const float4*)(bp2 + N);
    };
    auto convert_store = [&](uint32_t* buf) {
        uint32_t* Ah = buf;
        uint32_t* Al = buf + A_TILE_U32;
        uint32_t* Bh = buf + 2 * A_TILE_U32;
        uint32_t* Bl = Bh + B_TILE_U32;
        {
            uint32_t hh[8], ll[8];
            #pragma unroll
            for (int p = 0; p < 8; p++) {
                float x0 = aR[2 * p], x1 = aR[2 * p + 1];
                uint32_t hv = pack2(x0, x1);
                float f0, f1; unpack2(hv, f0, f1);
                hh[p] = hv;
                ll[p] = pack2(x0 - f0, x1 - f1);
            }
            int idx = a_row * A_STRIDE + a_half * 8;
            *(uint4*)&Ah[idx]     = *(uint4*)&hh[0];
            *(uint4*)&Ah[idx + 4] = *(uint4*)&hh[4];
            *(uint4*)&Al[idx]     = *(uint4*)&ll[0];
            *(uint4*)&Al[idx + 4] = *(uint4*)&ll[4];
        }
        {
            uint32_t hh[4], ll[4];
            #pragma unroll
            for (int j = 0; j < 4; j++) {
                float x0 = bR[j], x1 = bR[4 + j];   // k even, k odd
                uint32_t hv = pack2(x0, x1);
                float f0, f1; unpack2(hv, f0, f1);
                hh[j] = hv;
                ll[j] = pack2(x0 - f0, x1 - f1);
            }
            int idx = b_kp * B_STRIDE + b_nc;
            *(uint4*)&Bh[idx] = *(uint4*)&hh[0];
            *(uint4*)&Bl[idx] = *(uint4*)&ll[0];
        }
    };

    int nst = K / BK;
    load_regs(0);
    convert_store(bufs[0]);

    for (int s = 0; s < nst; s++) {
        uint32_t* buf = bufs[s & 1];
        uint32_t* Ah = buf;
        uint32_t* Al = buf + A_TILE_U32;
        uint32_t* Bh = buf + 2 * A_TILE_U32;
        uint32_t* Bl = Bh + B_TILE_U32;
        __syncthreads();
        if (s + 1 < nst) load_regs((s + 1) * BK);

        #pragma unroll
        for (int ks = 0; ks < 2; ks++) {
            uint32_t bh[4][2], bl[4][2];
            #pragma unroll
            for (int nt = 0; nt < 4; nt++) {
                int n = wn * 32 + nt * 8 + g;
                int k0 = (ks * 8 + c) * B_STRIDE + n;
                int k1 = (ks * 8 + c + 4) * B_STRIDE + n;
                bh[nt][0] = Bh[k0]; bh[nt][1] = Bh[k1];
                bl[nt][0] = Bl[k0]; bl[nt][1] = Bl[k1];
            }
            #pragma unroll
            for (int mt = 0; mt < 2; mt++) {
                int row = wm * 32 + mt * 16 + g;
                int i0 = row * A_STRIDE + ks * 8 + c;
                int i1 = (row + 8) * A_STRIDE + ks * 8 + c;
                uint32_t ah[4], al[4];
                ah[0] = Ah[i0]; ah[1] = Ah[i1]; ah[2] = Ah[i0 + 4]; ah[3] = Ah[i1 + 4];
                al[0] = Al[i0]; al[1] = Al[i1]; al[2] = Al[i0 + 4]; al[3] = Al[i1 + 4];
                #pragma unroll
                for (int nt = 0; nt < 4; nt++) {
                    mma_bf16(acc[mt][nt], ah, bh[nt]);
                    mma_bf16(acc[mt][nt], ah, bl[nt]);
                    mma_bf16(acc[mt][nt], al, bh[nt]);
                }
            }
        }
        if (s + 1 < nst) convert_store(bufs[(s + 1) & 1]);
    }

    #pragma unroll
    for (int mt = 0; mt < 2; mt++) {
        int r = m0 + wm * 32 + mt * 16 + g;
        #pragma unroll
        for (int nt = 0; nt < 4; nt++) {
            int col = n0 + wn * 32 + nt * 8 + c * 2;
            if (r < m)
                *(float2*)&Cb[(size_t)r * N + col] = make_float2(acc[mt][nt][0], acc[mt][nt][1]);
            if (r + 8 < m)
                *(float2*)&Cb[(size_t)(r + 8) * N + col] = make_float2(acc[mt][nt][2], acc[mt][nt][3]);
        }
    }
}

// ---------------- tensor-core flash attention (3xbf16 both GEMMs) --------------
#define KV_STR 36

__global__ void __launch_bounds__(128)
attn_tc(const float* __restrict__ qkv, float* __restrict__ o) {
    __shared__ uint32_t Kh[64 * KV_STR], Kl[64 * KV_STR];
    __shared__ uint32_t Vh[64 * KV_STR], Vl[64 * KV_STR];
    int qt = blockIdx.x, h = blockIdx.y;
    int tid = threadIdx.x, warp = tid >> 5, lane = tid & 31;
    int g = lane >> 2, c = lane & 3;
    int kvh = h >> 2;

    uint32_t Qh[4][4], Ql[4][4];
    {
        int r0 = qt * 64 + warp * 16 + g;
        const float* q0 = qkv + (size_t)r0 * QKVN + h * HD;
        const float* q1 = q0 + 8 * QKVN;
        #pragma unroll
        for (int ks = 0; ks < 4; ks++) {
            #pragma unroll
            for (int half = 0; half < 2; half++) {
                int d = ks * 16 + half * 8 + 2 * c;
                float x0 = q0[d] * 0.125f, x1 = q0[d + 1] * 0.125f;
                float y0 = q1[d] * 0.125f, y1 = q1[d + 1] * 0.125f;
                uint32_t hx = pack2(x0, x1), hy = pack2(y0, y1);
                float fx0, fx1, fy0, fy1;
                unpack2(hx, fx0, fx1);
                unpack2(hy, fy0, fy1);
                Qh[ks][half * 2]     = hx;
                Qh[ks][half * 2 + 1] = hy;
                Ql[ks][half * 2]     = pack2(x0 - fx0, x1 - fx1);
                Ql[ks][half * 2 + 1] = pack2(y0 - fy0, y1 - fy1);
            }
        }
    }

    float acc[8][4];
    #pragma unroll
    for (int nt = 0; nt < 8; nt++)
        #pragma unroll
        for (int q = 0; q < 4; q++) acc[nt][q] = 0.f;
    float m0 = -1e30f, m1 = -1e30f, l0 = 0.f, l1 = 0.f;

    for (int kt = 0; kt <= qt; kt++) {
        {
            int tok = tid >> 1, half = tid & 1;
            const float* kp = qkv + (size_t)(kt * 64 + tok) * QKVN + 2048 + kvh * HD + half * 32;
            float v[32];
            #pragma unroll
            for (int j = 0; j < 8; j++) ((float4*)v)[j] = ((const float4*)kp)[j];
            int base = tok * KV_STR + half * 16;
            #pragma unroll
            for (int j = 0; j < 16; j++) {
                uint32_t hv = pack2(v[2 * j], v[2 * j + 1]);
                float f0, f1; unpack2(hv, f0, f1);
                Kh[base + j] = hv;
                Kl[base + j] = pack2(v[2 * j] - f0, v[2 * j + 1] - f1);
            }
        }
        {
            const float* vp0 = qkv + (size_t)(kt * 64 + 2 * lane) * QKVN + 2560 + kvh * HD + warp * 16;
            const float* vp1 = vp0 + QKVN;
            float va[16], vb[16];
            #pragma unroll
            for (int j = 0; j < 4; j++) {
                ((float4*)va)[j] = ((const float4*)vp0)[j];
                ((float4*)vb)[j] = ((const float4*)vp1)[j];
            }
            #pragma unroll
            for (int i = 0; i < 16; i++) {
                uint32_t hv = pack2(va[i], vb[i]);
                float f0, f1; unpack2(hv, f0, f1);
                int idx = (warp * 16 + i) * KV_STR + lane;
                Vh[idx] = hv;
                Vl[idx] = pack2(va[i] - f0, vb[i] - f1);
            }
        }
        __syncthreads();

        float s[8][4];
        #pragma unroll
        for (int nt = 0; nt < 8; nt++)
            #pragma unroll
            for (int q = 0; q < 4; q++) s[nt][q] = 0.f;
        #pragma unroll
        for (int ks = 0; ks < 4; ks++) {
            #pragma unroll
            for (int nt = 0; nt < 8; nt++) {
                int idx = (nt * 8 + g) * KV_STR + ks * 8 + c;
                uint32_t bh[2] = { Kh[idx], Kh[idx + 4] };
                uint32_t bl[2] = { Kl[idx], Kl[idx + 4] };
                mma_bf16(s[nt], Qh[ks], bh);
                mma_bf16(s[nt], Ql[ks], bh);
                mma_bf16(s[nt], Qh[ks], bl);
            }
        }
        if (kt == qt) {
            int row0 = warp * 16 + g, row1 = row0 + 8;
            #pragma unroll
            for (int nt = 0; nt < 8; nt++) {
                int col = nt * 8 + 2 * c;
                if (col > row0)     s[nt][0] = -1e30f;
                if (col + 1 > row0) s[nt][1] = -1e30f;
                if (col > row1)     s[nt][2] = -1e30f;
                if (col + 1 > row1) s[nt][3] = -1e30f;
            }
        }
        float mx0 = -1e30f, mx1 = -1e30f;
        #pragma unroll
        for (int nt = 0; nt < 8; nt++) {
            mx0 = fmaxf(mx0, fmaxf(s[nt][0], s[nt][1]));
            mx1 = fmaxf(mx1, fmaxf(s[nt][2], s[nt][3]));
        }
        mx0 = fmaxf(mx0, __shfl_xor_sync(0xffffffffu, mx0, 1));
        mx0 = fmaxf(mx0, __shfl_xor_sync(0xffffffffu, mx0, 2));
        mx1 = fmaxf(mx1, __shfl_xor_sync(0xffffffffu, mx1, 1));
        mx1 = fmaxf(mx1, __shfl_xor_sync(0xffffffffu, mx1, 2));
        float mn0 = fmaxf(m0, mx0), mn1 = fmaxf(m1, mx1);
        float sc0 = expf(m0 - mn0), sc1 = expf(m1 - mn1);
        m0 = mn0; m1 = mn1;
        l0 *= sc0; l1 *= sc1;
        #pragma unroll
        for (int nt = 0; nt < 8; nt++) {
            acc[nt][0] *= sc0; acc[nt][1] *= sc0;
            acc[nt][2] *= sc1; acc[nt][3] *= sc1;
        }
        #pragma unroll
        for (int nt = 0; nt < 8; nt++) {
            s[nt][0] = expf(s[nt][0] - m0);
            s[nt][1] = expf(s[nt][1] - m0);
            s[nt][2] = expf(s[nt][2] - m1);
            s[nt][3] = expf(s[nt][3] - m1);
            l0 += s[nt][0] + s[nt][1];
            l1 += s[nt][2] + s[nt][3];
        }
        uint32_t Ph[4][4], Pl[4][4];
        #pragma unroll
        for (int j = 0; j < 4; j++) {
            #pragma unroll
            for (int q = 0; q < 4; q++) {
                int nt = 2 * j + (q >> 1);
                float x0 = s[nt][(q & 1) * 2], x1 = s[nt][(q & 1) * 2 + 1];
                uint32_t hv = pack2(x0, x1);
                float f0, f1; unpack2(hv, f0, f1);
                Ph[j][q] = hv;
                Pl[j][q] = pack2(x0 - f0, x1 - f1);
            }
        }
        #pragma unroll
        for (int j = 0; j < 4; j++) {
            #pragma unroll
            for (int nt = 0; nt < 8; nt++) {
                int idx = (nt * 8 + g) * KV_STR + j * 8 + c;
                uint32_t bh[2] = { Vh[idx], Vh[idx + 4] };
                uint32_t bl[2] = { Vl[idx], Vl[idx + 4] };
                mma_bf16(acc[nt], Ph[j], bh);
                mma_bf16(acc[nt], Pl[j], bh);
                mma_bf16(acc[nt], Ph[j], bl);
            }
        }
        __syncthreads();
    }

    l0 += __shfl_xor_sync(0xffffffffu, l0, 1);
    l0 += __shfl_xor_sync(0xffffffffu, l0, 2);
    l1 += __shfl_xor_sync(0xffffffffu, l1, 1);
    l1 += __shfl_xor_sync(0xffffffffu, l1, 2);
    float inv0 = 1.f / l0, inv1 = 1.f / l1;
    int r0 = qt * 64 + warp * 16 + g;
    float* op0 = o + (size_t)r0 * (NH * HD) + h * HD;
    float* op1 = op0 + 8 * (NH * HD);
    #pragma unroll
    for (int nt = 0; nt < 8; nt++) {
        *(float2*)&op0[nt * 8 + 2 * c] = make_float2(acc[nt][0] * inv0, acc[nt][1] * inv0);
        *(float2*)&op1[nt * 8 + 2 * c] = make_float2(acc[nt][2] * inv1, acc[nt][3] * inv1);
    }
}

// ---------------- small kernels ------------------------------------------------
__global__ void zero_cnt_kernel() {
    if (threadIdx.x < NE) g_cnt[threadIdx.x] = 0;
}

__global__ void pack_qkv_kernel(const float* __restrict__ Wq, const float* __restrict__ Wk,
                                const float* __restrict__ Wv) {
    int idx = blockIdx.x * blockDim.x + threadIdx.x;
    if (idx >= DIM * QKVN) return;
    int k = idx / QKVN, n = idx % QKVN;
    float v;
    if (n < 2048)      v = Wq[k * 2048 + n];
    else if (n < 2560) v = Wk[k * 512 + (n - 2048)];
    else               v = Wv[k * 512 + (n - 2560)];
    g_wqkv[idx] = v;
}

__global__ void rmsnorm_kernel(const float* __restrict__ x,
                               const float* __restrict__ w,
                               float* __restrict__ o) {
    int row = blockIdx.x;
    const float* xr = x + (size_t)row * DIM;
    float s = 0.f;
    for (int i = threadIdx.x; i < DIM; i += blockDim.x) {
        float v = xr[i];
        s += v * v;
    }
    __shared__ float red[32];
    int lane = threadIdx.x & 31, wid = threadIdx.x >> 5;
    #pragma unroll
    for (int off = 16; off; off >>= 1) s += __shfl_down_sync(0xffffffffu, s, off);
    if (lane == 0) red[wid] = s;
    __syncthreads();
    if (wid == 0) {
        float t = (lane < (blockDim.x >> 5)) ? red[lane] : 0.f;
        #pragma unroll
        for (int off = 16; off; off >>= 1) t += __shfl_down_sync(0xffffffffu, t, off);
        if (lane == 0) red[0] = t;
    }
    __syncthreads();
    float scale = rsqrtf(red[0] / (float)DIM + 1e-5f);
    float* orow = o + (size_t)row * DIM;
    for (int i = threadIdx.x; i < DIM; i += blockDim.x)
        orow[i] = xr[i] * scale * w[i];
}

__global__ void add_kernel(const float* __restrict__ a, const float* __restrict__ b,
                           float* __restrict__ o, int n) {
    int i = blockIdx.x * blockDim.x + threadIdx.x;
    if (i < n) o[i] = a[i] + b[i];
}

__global__ void rope_kernel(float* __restrict__ x, const int* __restrict__ pos,
                            int heads, int stride, int off) {
    int idx = blockIdx.x * blockDim.x + threadIdx.x;
    int total = SEQ * heads * (HD / 2);
    if (idx >= total) return;
    int d = idx & 31;
    int t = idx >> 5;
    int h = t % heads;
    int s = t / heads;
    double invd = pow(1.0e6, -(double)d / 32.0);
    float ang = (float)((double)pos[s] * invd);
    float cs, sn;
    sincosf(ang, &sn, &cs);
    float* p = x + (size_t)s * stride + off + h * HD;
    float x1 = p[d], x2 = p[d + 32];
    p[d]      = x1 * cs - x2 * sn;
    p[d + 32] = x2 * cs + x1 * sn;
}

__global__ void router_kernel(const float* __restrict__ x, const float* __restrict__ Wr) {
    int warp = (blockIdx.x * blockDim.x + threadIdx.x) >> 5;
    int lane = threadIdx.x & 31;
    if (warp >= SEQ) return;
    const float* xr = x + (size_t)warp * DIM;
    float acc[NE];
    #pragma unroll
    for (int e = 0; e < NE; e++) acc[e] = 0.f;
    for (int d = lane; d < DIM; d += 32) {
        float xv = xr[d];
        #pragma unroll
        for (int e = 0; e < NE; e++) acc[e] += xv * Wr[d * NE + e];
    }
    #pragma unroll
    for (int e = 0; e < NE; e++)
        #pragma unroll
        for (int off = 16; off; off >>= 1)
            acc[e] += __shfl_down_sync(0xffffffffu, acc[e], off);
    if (lane == 0) {
        int i1 = 0;
        #pragma unroll
        for (int e = 1; e < NE; e++) if (acc[e] > acc[i1]) i1 = e;
        int i2 = (i1 == 0) ? 1 : 0;
        #pragma unroll
        for (int e = 0; e < NE; e++) if (e != i1 && acc[e] > acc[i2]) i2 = e;
        float w1 = 1.f / (1.f + expf(acc[i2] - acc[i1]));
        int s0 = atomicAdd(&g_cnt[i1], 1);
        int s1 = atomicAdd(&g_cnt[i2], 1);
        g_eid[warp * 2]  = i1; g_eid[warp * 2 + 1]  = i2;
        g_slot[warp * 2] = s0; g_slot[warp * 2 + 1] = s1;
        g_w[warp * 2]    = w1; g_w[warp * 2 + 1]    = 1.f - w1;
    }
}

__global__ void gather_kernel(const float* __restrict__ x) {
    int pair = blockIdx.x;
    int n = pair >> 1, j = pair & 1;
    int e = g_eid[n * 2 + j], s = g_slot[n * 2 + j];
    const float4* src = (const float4*)(x + (size_t)n * DIM);
    float4* dst = (float4*)(g_xe + ((size_t)e * CAP + s) * DIM);
    for (int i = threadIdx.x; i < DIM / 4; i += blockDim.x) dst[i] = src[i];
}

__global__ void silu_mul_kernel() {
    int e = blockIdx.z;
    int r = blockIdx.y;
    if (r >= g_cnt[e]) return;
    size_t base = ((size_t)e * CAP + r) * FF;
    int c = blockIdx.x * blockDim.x + threadIdx.x;
    float g = g_gate[base + c];
    float u = g_up[base + c];
    g_gate[base + c] = (g / (1.f + expf(-g))) * u;
}

__global__ void combine_kernel(float* __restrict__ out) {
    int idx = blockIdx.x * blockDim.x + threadIdx.x;
    if (idx >= SEQ * DIM) return;
    int n = idx >> 11;
    int d = idx & (DIM - 1);
    int e0 = g_eid[n * 2],  e1 = g_eid[n * 2 + 1];
    int s0 = g_slot[n * 2], s1 = g_slot[n * 2 + 1];
    out[idx] = g_h2[idx]
             + g_w[n * 2]     * g_down[((size_t)e0 * CAP + s0) * DIM + d]
             + g_w[n * 2 + 1] * g_down[((size_t)e1 * CAP + s1) * DIM + d];
}

// ---------------- launch -------------------------------------------------------
extern "C" void kernel_launch(void* const* d_in, const int* in_sizes, int n_in,
                              void* d_out, int out_size) {
    const float* hidden = (const float*)d_in[0];
    const int*   pos    = (const int*)  d_in[1];
    const float* ln1    = (const float*)d_in[2];
    const float* Wq     = (const float*)d_in[3];
    const float* Wk     = (const float*)d_in[4];
    const float* Wv     = (const float*)d_in[5];
    const float* Wo     = (const float*)d_in[6];
    const float* ln2    = (const float*)d_in[7];
    const float* Wr     = (const float*)d_in[8];
    const float* W1     = (const float*)d_in[9];
    const float* W3     = (const float*)d_in[10];
    const float* W2     = (const float*)d_in[11];
    float* out = (float*)d_out;

    float *p_hn, *p_wqkv, *p_qkv, *p_attn, *p_h2, *p_hn2, *p_xe, *p_gate, *p_up, *p_down;
    cudaGetSymbolAddress((void**)&p_hn,   g_hn);
    cudaGetSymbolAddress((void**)&p_wqkv, g_wqkv);
    cudaGetSymbolAddress((void**)&p_qkv,  g_qkv);
    cudaGetSymbolAddress((void**)&p_attn, g_attn);
    cudaGetSymbolAddress((void**)&p_h2,   g_h2);
    cudaGetSymbolAddress((void**)&p_hn2,  g_hn2);
    cudaGetSymbolAddress((void**)&p_xe,   g_xe);
    cudaGetSymbolAddress((void**)&p_gate, g_gate);
    cudaGetSymbolAddress((void**)&p_up,   g_up);
    cudaGetSymbolAddress((void**)&p_down, g_down);
    int* p_cnt;
    cudaGetSymbolAddress((void**)&p_cnt, g_cnt);

    static int smem_set = 0;
    if (!smem_set) {
        cudaFuncSetAttribute(gemm_tc, cudaFuncAttributeMaxDynamicSharedMemorySize, GSMEM_BYTES);
        smem_set = 1;
    }

    zero_cnt_kernel<<<1, 32>>>();
    rmsnorm_kernel<<<SEQ, 256>>>(hidden, ln1, p_hn);
    pack_qkv_kernel<<<(DIM * QKVN + 255) / 256, 256>>>(Wq, Wk, Wv);

    // QKV projection: [2048,2048] @ [2048,3072]
    gemm_tc<<<dim3(QKVN / BN, SEQ / BM, 1), 256, GSMEM_BYTES>>>(
        p_hn, p_wqkv, p_qkv, SEQ, QKVN, DIM, 0, 0, 0, 0);

    rope_kernel<<<(SEQ * NH * (HD / 2) + 255) / 256, 256>>>(p_qkv, pos, NH, QKVN, 0);
    rope_kernel<<<(SEQ * KVH * (HD / 2) + 255) / 256, 256>>>(p_qkv, pos, KVH, QKVN, 2048);

    attn_tc<<<dim3(SEQ / 64, NH, 1), 128>>>(p_qkv, p_attn);

    // O projection + residual
    gemm_tc<<<dim3(DIM / BN, SEQ / BM, 1), 256, GSMEM_BYTES>>>(
        p_attn, Wo, p_hn, SEQ, DIM, NH * HD, 0, 0, 0, 0);
    add_kernel<<<(SEQ * DIM + 255) / 256, 256>>>(hidden, p_hn, p_h2, SEQ * DIM);

    rmsnorm_kernel<<<SEQ, 256>>>(p_h2, ln2, p_hn2);
    router_kernel<<<(SEQ * 32 + 255) / 256, 256>>>(p_hn2, Wr);
    gather_kernel<<<SEQ * 2, 256>>>(p_hn2);

    // expert GEMMs (device-count early exit)
    gemm_tc<<<dim3(FF / BN, CAP / BM, NE), 256, GSMEM_BYTES>>>(
        p_xe, W1, p_gate, CAP, FF, DIM, p_cnt,
        (size_t)CAP * DIM, (size_t)DIM * FF, (size_t)CAP * FF);
    gemm_tc<<<dim3(FF / BN, CAP / BM, NE), 256, GSMEM_BYTES>>>(
        p_xe, W3, p_up, CAP, FF, DIM, p_cnt,
        (size_t)CAP * DIM, (size_t)DIM * FF, (size_t)CAP * FF);
    silu_mul_kernel<<<dim3(FF / 256, CAP, NE), 256>>>();
    gemm_tc<<<dim3(DIM / BN, CAP / BM, NE), 256, GSMEM_BYTES>>>(
        p_gate, W2, p_down, CAP, DIM, FF, p_cnt,
        (size_t)CAP * FF, (size_t)FF * DIM, (size_t)CAP * DIM);

    combine_kernel<<<(SEQ * DIM + 255) / 256, 256>>>(out);
}

// round 12
// speedup vs baseline: 1.1147x; 1.1058x over previous
#include <cuda_runtime.h>
#include <cuda_bf16.h>
#include <math.h>
#include <stdint.h>

#define DIM   2048
#define SEQ   2048
#define NH    32
#define KVH   8
#define HD    64
#define NE    8
#define FF    7168
#define CAP   2048
#define QKVN  3072
#define DW    (DIM/2)    // 1024 packed words per DIM row
#define FW    (FF/2)     // 3584 packed words per FF row

// ---------------- scratch (device globals) ------------------------------------
static __device__ uint32_t g_hnhi [SEQ * DW];
static __device__ uint32_t g_hnlo [SEQ * DW];
static __device__ float    g_wqkv [DIM * QKVN];
static __device__ float    g_qkv  [SEQ * QKVN];
static __device__ uint32_t g_athi [SEQ * DW];
static __device__ uint32_t g_atlo [SEQ * DW];
static __device__ float    g_o    [SEQ * DIM];
static __device__ float    g_h2   [SEQ * DIM];
static __device__ float    g_hn2  [SEQ * DIM];
static __device__ uint32_t g_hn2hi[SEQ * DW];
static __device__ uint32_t g_hn2lo[SEQ * DW];
static __device__ uint32_t g_xehi [(size_t)NE * CAP * DW];
static __device__ uint32_t g_xelo [(size_t)NE * CAP * DW];
static __device__ float    g_gate [(size_t)NE * CAP * FF];
static __device__ float    g_up   [(size_t)NE * CAP * FF];
static __device__ uint32_t g_acthi[(size_t)NE * CAP * FW];
static __device__ uint32_t g_actlo[(size_t)NE * CAP * FW];
static __device__ float    g_down [(size_t)NE * CAP * DIM];
static __device__ int      g_cnt  [NE];
static __device__ int      g_eid  [SEQ * 2];
static __device__ int      g_slot [SEQ * 2];
static __device__ float    g_w    [SEQ * 2];

// ---------------- helpers ------------------------------------------------------
__device__ __forceinline__ uint32_t pack2(float x0, float x1) {
    uint32_t u;
    asm("cvt.rn.bf16x2.f32 %0, %1, %2;" : "=r"(u) : "f"(x1), "f"(x0));
    return u;
}
__device__ __forceinline__ void unpack2(uint32_t u, float& f0, float& f1) {
    __nv_bfloat162 t = *reinterpret_cast<__nv_bfloat162*>(&u);
    f0 = __bfloat162float(t.x);
    f1 = __bfloat162float(t.y);
}
__device__ __forceinline__ void hilo(float x0, float x1, uint32_t& h, uint32_t& l) {
    h = pack2(x0, x1);
    float f0, f1; unpack2(h, f0, f1);
    l = pack2(x0 - f0, x1 - f1);
}
__device__ __forceinline__ void mma_bf16(float* d, const uint32_t* a, const uint32_t* b) {
    asm volatile(
        "mma.sync.aligned.m16n8k16.row.col.f32.bf16.bf16.f32 "
        "{%0,%1,%2,%3}, {%4,%5,%6,%7}, {%8,%9}, {%0,%1,%2,%3};"
        : "+f"(d[0]), "+f"(d[1]), "+f"(d[2]), "+f"(d[3])
        : "r"(a[0]), "r"(a[1]), "r"(a[2]), "r"(a[3]), "r"(b[0]), "r"(b[1]));
}
__device__ __forceinline__ void ldsm_x4(uint32_t* r, uint32_t addr) {
    asm volatile("ldmatrix.sync.aligned.m8n8.x4.shared.b16 {%0,%1,%2,%3}, [%4];"
        : "=r"(r[0]), "=r"(r[1]), "=r"(r[2]), "=r"(r[3]) : "r"(addr));
}
__device__ __forceinline__ uint32_t smem_u32(const void* p) {
    uint32_t a;
    asm("{ .reg .u64 t; cvta.to.shared.u64 t, %1; cvt.u32.u64 %0, t; }" : "=r"(a) : "l"(p));
    return a;
}
__device__ __forceinline__ void cp_async16(uint32_t dst, const void* src) {
    asm volatile("cp.async.cg.shared.global [%0], [%1], 16;" :: "r"(dst), "l"(src) : "memory");
}

// --- 3xBF16 GEMM: 128x64x32 tile, 256 thr, 2 CTA/SM, ldmatrix + cp.async A ----
#define BM 128
#define BN 64
#define BK 32
#define A_STR 20                      // u32 per A row (16 kpair words + 4 pad)
#define B_STR 20                      // u32 per B n-row (16 kpair words + 4 pad)
#define A_TILE (BM * A_STR)           // 2560 u32 (per hi / per lo)
#define B_TILE (BN * B_STR)           // 1280 u32
#define STAGE_U32 (2 * A_TILE + 2 * B_TILE)   // 7680
#define GSMEM_BYTES (2 * STAGE_U32 * 4)       // 61440

__global__ void __launch_bounds__(256, 2)
gemm_tc(const uint32_t* __restrict__ Ahi, const uint32_t* __restrict__ Alo,
        const float* __restrict__ B, float* __restrict__ C,
        int M, int N, int K, const int* __restrict__ cnt,
        size_t sA, size_t sB, size_t sC) {
    int e = blockIdx.z;
    int m = cnt ? cnt[e] : M;
    int m0 = blockIdx.y * BM;
    if (m0 >= m) return;
    int n0 = blockIdx.x * BN;
    int Kw = K >> 1;

    extern __shared__ uint32_t smu[];
    uint32_t sbase = smem_u32(smu);

    const uint32_t* Ahb = Ahi + sA * (size_t)e;
    const uint32_t* Alb = Alo + sA * (size_t)e;
    const float*    Bb  = B + sB * (size_t)e;
    float*          Cb  = C + sC * (size_t)e;

    int tid = threadIdx.x;
    int warp = tid >> 5, lane = tid & 31;
    int wm = warp >> 1, wn = warp & 1;     // 4x2 warp grid, warp tile 32x32
    int g = lane >> 2, c = lane & 3;

    // A copy role: half-row (8 words hi + 8 lo) per thread via cp.async
    int a_row = tid >> 1, a_half = tid & 1;
    int a_src = m0 + a_row < m ? m0 + a_row : m - 1;
    const uint32_t* pAh = Ahb + (size_t)a_src * Kw + a_half * 8;
    const uint32_t* pAl = Alb + (size_t)a_src * Kw + a_half * 8;
    uint32_t dA = sbase + (uint32_t)(a_row * A_STR + a_half * 8) * 4;

    // B copy role: one n column, 4 kpairs (8 consecutive k) per thread
    int bn = tid & 63, bkg = tid >> 6;
    const float* pB = Bb + n0 + bn;
    uint32_t* BhS = smu + 2 * A_TILE + bn * B_STR + bkg * 4;   // + buf offset later

    // ldmatrix lane addresses (byte offsets within a stage buffer)
    int aRowOff = ((lane >> 3) & 1) * 8 + (lane & 7);
    int aKpOff  = ((lane >> 4) & 1) * 4;
    uint32_t aB0 = (uint32_t)(((wm * 32 + 0 * 16 + aRowOff) * A_STR + aKpOff) * 4);
    uint32_t aB1 = (uint32_t)(((wm * 32 + 1 * 16 + aRowOff) * A_STR + aKpOff) * 4);
    int bNOff  = ((lane >> 4) & 1) * 8 + (lane & 7);
    int bKpOff = ((lane >> 3) & 1) * 4;
    uint32_t bB0 = (uint32_t)((2 * A_TILE + (wn * 32 + 0 * 16 + bNOff) * B_STR + bKpOff) * 4);
    uint32_t bB1 = (uint32_t)((2 * A_TILE + (wn * 32 + 1 * 16 + bNOff) * B_STR + bKpOff) * 4);

    float acc[2][4][4];
    #pragma unroll
    for (int i = 0; i < 2; i++)
        #pragma unroll
        for (int j = 0; j < 4; j++)
            #pragma unroll
            for (int q = 0; q < 4; q++) acc[i][j][q] = 0.f;

    float bF[8];

    auto cpasyncA = [&](int s, uint32_t bufB) {
        int kw = s * 16;
        uint32_t d = dA + bufB;
        cp_async16(d,                      pAh + kw);
        cp_async16(d + 16,                 pAh + kw + 4);
        cp_async16(d + A_TILE * 4,         pAl + kw);
        cp_async16(d + A_TILE * 4 + 16,    pAl + kw + 4);
        asm volatile("cp.async.commit_group;" ::: "memory");
    };
    auto ldgB = [&](int s) {
        int k0 = s * BK + bkg * 8;
        #pragma unroll
        for (int j = 0; j < 8; j++) bF[j] = pB[(size_t)(k0 + j) * N];
    };
    auto storeB = [&](int bufIdx) {
        uint32_t hh[4], ll[4];
        #pragma unroll
        for (int j = 0; j < 4; j++) hilo(bF[2 * j], bF[2 * j + 1], hh[j], ll[j]);
        uint32_t* p = BhS + bufIdx * STAGE_U32;
        *(uint4*)p            = *(uint4*)hh;
        *(uint4*)(p + B_TILE) = *(uint4*)ll;
    };

    int nst = K / BK;
    cpasyncA(0, 0);
    ldgB(0);
    asm volatile("cp.async.wait_group 0;" ::: "memory");
    storeB(0);
    __syncthreads();

    for (int s = 0; s < nst; s++) {
        int bi = s & 1;
        uint32_t bufB = (uint32_t)(bi * STAGE_U32 * 4);
        if (s + 1 < nst) {
            cpasyncA(s + 1, bufB ^ (uint32_t)(STAGE_U32 * 4));
            ldgB(s + 1);
        }

        #pragma unroll
        for (int ks = 0; ks < 2; ks++) {
            uint32_t ko = (uint32_t)(ks * 32);   // 8 words
            uint32_t bh[4][2], bl[4][2];
            {
                uint32_t r[4];
                ldsm_x4(r, sbase + bufB + bB0 + ko);
                bh[0][0] = r[0]; bh[0][1] = r[1]; bh[1][0] = r[2]; bh[1][1] = r[3];
                ldsm_x4(r, sbase + bufB + bB0 + (uint32_t)(B_TILE * 4) + ko);
                bl[0][0] = r[0]; bl[0][1] = r[1]; bl[1][0] = r[2]; bl[1][1] = r[3];
                ldsm_x4(r, sbase + bufB + bB1 + ko);
                bh[2][0] = r[0]; bh[2][1] = r[1]; bh[3][0] = r[2]; bh[3][1] = r[3];
                ldsm_x4(r, sbase + bufB + bB1 + (uint32_t)(B_TILE * 4) + ko);
                bl[2][0] = r[0]; bl[2][1] = r[1]; bl[3][0] = r[2]; bl[3][1] = r[3];
            }
            #pragma unroll
            for (int mt = 0; mt < 2; mt++) {
                uint32_t aBase = mt ? aB1 : aB0;
                uint32_t ah[4], al[4];
                ldsm_x4(ah, sbase + bufB + aBase + ko);
                ldsm_x4(al, sbase + bufB + aBase + (uint32_t)(A_TILE * 4) + ko);
                #pragma unroll
                for (int nt = 0; nt < 4; nt++) {
                    mma_bf16(acc[mt][nt], ah, bh[nt]);
                    mma_bf16(acc[mt][nt], ah, bl[nt]);
                    mma_bf16(acc[mt][nt], al, bh[nt]);
                }
            }
        }
        if (s + 1 < nst) {
            asm volatile("cp.async.wait_group 0;" ::: "memory");
            storeB(bi ^ 1);
        }
        __syncthreads();
    }

    #pragma unroll
    for (int mt = 0; mt < 2; mt++) {
        int r = m0 + wm * 32 + mt * 16 + g;
        #pragma unroll
        for (int nt = 0; nt < 4; nt++) {
            int col = n0 + wn * 32 + nt * 8 + c * 2;
            if (r < m)
                *(float2*)&Cb[(size_t)r * N + col] = make_float2(acc[mt][nt][0], acc[mt][nt][1]);
            if (r + 8 < m)
                *(float2*)&Cb[(size_t)(r + 8) * N + col] = make_float2(acc[mt][nt][2], acc[mt][nt][3]);
        }
    }
}

// ---------------- tensor-core flash attention (3xbf16 both GEMMs) --------------
#define KV_STR 36

__global__ void __launch_bounds__(128)
attn_tc(const float* __restrict__ qkv, uint32_t* __restrict__ ohi, uint32_t* __restrict__ olo) {
    __shared__ uint32_t Kh[64 * KV_STR], Kl[64 * KV_STR];
    __shared__ uint32_t Vh[64 * KV_STR], Vl[64 * KV_STR];
    int qt = blockIdx.x, h = blockIdx.y;
    int tid = threadIdx.x, warp = tid >> 5, lane = tid & 31;
    int g = lane >> 2, c = lane & 3;
    int kvh = h >> 2;

    uint32_t Qh[4][4], Ql[4][4];
    {
        int r0 = qt * 64 + warp * 16 + g;
        const float* q0 = qkv + (size_t)r0 * QKVN + h * HD;
        const float* q1 = q0 + 8 * QKVN;
        #pragma unroll
        for (int ks = 0; ks < 4; ks++) {
            #pragma unroll
            for (int half = 0; half < 2; half++) {
                int d = ks * 16 + half * 8 + 2 * c;
                hilo(q0[d] * 0.125f, q0[d + 1] * 0.125f, Qh[ks][half * 2], Ql[ks][half * 2]);
                hilo(q1[d] * 0.125f, q1[d + 1] * 0.125f, Qh[ks][half * 2 + 1], Ql[ks][half * 2 + 1]);
            }
        }
    }

    float acc[8][4];
    #pragma unroll
    for (int nt = 0; nt < 8; nt++)
        #pragma unroll
        for (int q = 0; q < 4; q++) acc[nt][q] = 0.f;
    float m0 = -1e30f, m1 = -1e30f, l0 = 0.f, l1 = 0.f;

    for (int kt = 0; kt <= qt; kt++) {
        {
            int tok = tid >> 1, half = tid & 1;
            const float* kp = qkv + (size_t)(kt * 64 + tok) * QKVN + 2048 + kvh * HD + half * 32;
            float v[32];
            #pragma unroll
            for (int j = 0; j < 8; j++) ((float4*)v)[j] = ((const float4*)kp)[j];
            int base = tok * KV_STR + half * 16;
            #pragma unroll
            for (int j = 0; j < 16; j++)
                hilo(v[2 * j], v[2 * j + 1], Kh[base + j], Kl[base + j]);
        }
        {
            const float* vp0 = qkv + (size_t)(kt * 64 + 2 * lane) * QKVN + 2560 + kvh * HD + warp * 16;
            const float* vp1 = vp0 + QKVN;
            float va[16], vb[16];
            #pragma unroll
            for (int j = 0; j < 4; j++) {
                ((float4*)va)[j] = ((const float4*)vp0)[j];
                ((float4*)vb)[j] = ((const float4*)vp1)[j];
            }
            #pragma unroll
            for (int i = 0; i < 16; i++) {
                int idx = (warp * 16 + i) * KV_STR + lane;
                hilo(va[i], vb[i], Vh[idx], Vl[idx]);
            }
        }
        __syncthreads();

        float s[8][4];
        #pragma unroll
        for (int nt = 0; nt < 8; nt++)
            #pragma unroll
            for (int q = 0; q < 4; q++) s[nt][q] = 0.f;
        #pragma unroll
        for (int ks = 0; ks < 4; ks++) {
            #pragma unroll
            for (int nt = 0; nt < 8; nt++) {
                int idx = (nt * 8 + g) * KV_STR + ks * 8 + c;
                uint32_t bh[2] = { Kh[idx], Kh[idx + 4] };
                uint32_t bl[2] = { Kl[idx], Kl[idx + 4] };
                mma_bf16(s[nt], Qh[ks], bh);
                mma_bf16(s[nt], Ql[ks], bh);
                mma_bf16(s[nt], Qh[ks], bl);
            }
        }
        if (kt == qt) {
            int row0 = warp * 16 + g, row1 = row0 + 8;
            #pragma unroll
            for (int nt = 0; nt < 8; nt++) {
                int col = nt * 8 + 2 * c;
                if (col > row0)     s[nt][0] = -1e30f;
                if (col + 1 > row0) s[nt][1] = -1e30f;
                if (col > row1)     s[nt][2] = -1e30f;
                if (col + 1 > row1) s[nt][3] = -1e30f;
            }
        }
        float mx0 = -1e30f, mx1 = -1e30f;
        #pragma unroll
        for (int nt = 0; nt < 8; nt++) {
            mx0 = fmaxf(mx0, fmaxf(s[nt][0], s[nt][1]));
            mx1 = fmaxf(mx1, fmaxf(s[nt][2], s[nt][3]));
        }
        mx0 = fmaxf(mx0, __shfl_xor_sync(0xffffffffu, mx0, 1));
        mx0 = fmaxf(mx0, __shfl_xor_sync(0xffffffffu, mx0, 2));
        mx1 = fmaxf(mx1, __shfl_xor_sync(0xffffffffu, mx1, 1));
        mx1 = fmaxf(mx1, __shfl_xor_sync(0xffffffffu, mx1, 2));
        float mn0 = fmaxf(m0, mx0), mn1 = fmaxf(m1, mx1);
        float sc0 = expf(m0 - mn0), sc1 = expf(m1 - mn1);
        m0 = mn0; m1 = mn1;
        l0 *= sc0; l1 *= sc1;
        #pragma unroll
        for (int nt = 0; nt < 8; nt++) {
            acc[nt][0] *= sc0; acc[nt][1] *= sc0;
            acc[nt][2] *= sc1; acc[nt][3] *= sc1;
        }
        #pragma unroll
        for (int nt = 0; nt < 8; nt++) {
            s[nt][0] = expf(s[nt][0] - m0);
            s[nt][1] = expf(s[nt][1] - m0);
            s[nt][2] = expf(s[nt][2] - m1);
            s[nt][3] = expf(s[nt][3] - m1);
            l0 += s[nt][0] + s[nt][1];
            l1 += s[nt][2] + s[nt][3];
        }
        uint32_t Ph[4][4], Pl[4][4];
        #pragma unroll
        for (int j = 0; j < 4; j++) {
            #pragma unroll
            for (int q = 0; q < 4; q++) {
                int nt = 2 * j + (q >> 1);
                hilo(s[nt][(q & 1) * 2], s[nt][(q & 1) * 2 + 1], Ph[j][q], Pl[j][q]);
            }
        }
        #pragma unroll
        for (int j = 0; j < 4; j++) {
            #pragma unroll
            for (int nt = 0; nt < 8; nt++) {
                int idx = (nt * 8 + g) * KV_STR + j * 8 + c;
                uint32_t bh[2] = { Vh[idx], Vh[idx + 4] };
                uint32_t bl[2] = { Vl[idx], Vl[idx + 4] };
                mma_bf16(acc[nt], Ph[j], bh);
                mma_bf16(acc[nt], Pl[j], bh);
                mma_bf16(acc[nt], Ph[j], bl);
            }
        }
        __syncthreads();
    }

    l0 += __shfl_xor_sync(0xffffffffu, l0, 1);
    l0 += __shfl_xor_sync(0xffffffffu, l0, 2);
    l1 += __shfl_xor_sync(0xffffffffu, l1, 1);
    l1 += __shfl_xor_sync(0xffffffffu, l1, 2);
    float inv0 = 1.f / l0, inv1 = 1.f / l1;
    int r0 = qt * 64 + warp * 16 + g;
    // packed epilogue: acc[nt][0..1] is a k-even/odd pair at word index h*32 + nt*4 + c
    #pragma unroll
    for (int nt = 0; nt < 8; nt++) {
        int w0 = r0 * DW + h * 32 + nt * 4 + c;
        int w1 = (r0 + 8) * DW + h * 32 + nt * 4 + c;
        uint32_t hv, lv;
        hilo(acc[nt][0] * inv0, acc[nt][1] * inv0, hv, lv);
        ohi[w0] = hv; olo[w0] = lv;
        hilo(acc[nt][2] * inv1, acc[nt][3] * inv1, hv, lv);
        ohi[w1] = hv; olo[w1] = lv;
    }
}

// ---------------- small kernels ------------------------------------------------
__global__ void zero_cnt_kernel() {
    if (threadIdx.x < NE) g_cnt[threadIdx.x] = 0;
}

__global__ void pack_qkv_kernel(const float* __restrict__ Wq, const float* __restrict__ Wk,
                                const float* __restrict__ Wv) {
    int idx = blockIdx.x * blockDim.x + threadIdx.x;
    if (idx >= DIM * QKVN) return;
    int k = idx / QKVN, n = idx % QKVN;
    float v;
    if (n < 2048)      v = Wq[k * 2048 + n];
    else if (n < 2560) v = Wk[k * 512 + (n - 2048)];
    else               v = Wv[k * 512 + (n - 2560)];
    g_wqkv[idx] = v;
}

// RMS scale for one row (256 threads)
__device__ __forceinline__ float rms_scale(const float* xr, int tid, int bdim) {
    float s = 0.f;
    for (int i = tid; i < DIM; i += bdim) {
        float v = xr[i];
        s += v * v;
    }
    __shared__ float red[32];
    int lane = tid & 31, wid = tid >> 5;
    #pragma unroll
    for (int off = 16; off; off >>= 1) s += __shfl_down_sync(0xffffffffu, s, off);
    if (lane == 0) red[wid] = s;
    __syncthreads();
    if (wid == 0) {
        float t = (lane < (bdim >> 5)) ? red[lane] : 0.f;
        #pragma unroll
        for (int off = 16; off; off >>= 1) t += __shfl_down_sync(0xffffffffu, t, off);
        if (lane == 0) red[0] = t;
    }
    __syncthreads();
    return rsqrtf(red[0] / (float)DIM + 1e-5f);
}

// rmsnorm -> packed hi/lo only (QKV A)
__global__ void rmsnorm_pack_kernel(const float* __restrict__ x, const float* __restrict__ w,
                                    uint32_t* __restrict__ hi, uint32_t* __restrict__ lo) {
    int row = blockIdx.x;
    const float* xr = x + (size_t)row * DIM;
    float scale = rms_scale(xr, threadIdx.x, blockDim.x);
    for (int p = threadIdx.x; p < DW; p += blockDim.x) {
        float x0 = xr[2 * p] * scale * w[2 * p];
        float x1 = xr[2 * p + 1] * scale * w[2 * p + 1];
        uint32_t h, l;
        hilo(x0, x1, h, l);
        hi[(size_t)row * DW + p] = h;
        lo[(size_t)row * DW + p] = l;
    }
}

// rmsnorm -> fp32 (router) + packed hi/lo (MoE A)
__global__ void rmsnorm_both_kernel(const float* __restrict__ x, const float* __restrict__ w,
                                    float* __restrict__ o,
                                    uint32_t* __restrict__ hi, uint32_t* __restrict__ lo) {
    int row = blockIdx.x;
    const float* xr = x + (size_t)row * DIM;
    float scale = rms_scale(xr, threadIdx.x, blockDim.x);
    for (int p = threadIdx.x; p < DW; p += blockDim.x) {
        float x0 = xr[2 * p] * scale * w[2 * p];
        float x1 = xr[2 * p + 1] * scale * w[2 * p + 1];
        o[(size_t)row * DIM + 2 * p]     = x0;
        o[(size_t)row * DIM + 2 * p + 1] = x1;
        uint32_t h, l;
        hilo(x0, x1, h, l);
        hi[(size_t)row * DW + p] = h;
        lo[(size_t)row * DW + p] = l;
    }
}

__global__ void add_kernel(const float* __restrict__ a, const float* __restrict__ b,
                           float* __restrict__ o, int n) {
    int i = blockIdx.x * blockDim.x + threadIdx.x;
    if (i < n) o[i] = a[i] + b[i];
}

__global__ void rope_kernel(float* __restrict__ x, const int* __restrict__ pos,
                            int heads, int stride, int off) {
    int idx = blockIdx.x * blockDim.x + threadIdx.x;
    int total = SEQ * heads * (HD / 2);
    if (idx >= total) return;
    int d = idx & 31;
    int t = idx >> 5;
    int h = t % heads;
    int s = t / heads;
    double invd = pow(1.0e6, -(double)d / 32.0);
    float ang = (float)((double)pos[s] * invd);
    float cs, sn;
    sincosf(ang, &sn, &cs);
    float* p = x + (size_t)s * stride + off + h * HD;
    float x1 = p[d], x2 = p[d + 32];
    p[d]      = x1 * cs - x2 * sn;
    p[d + 32] = x2 * cs + x1 * sn;
}

__global__ void router_kernel(const float* __restrict__ x, const float* __restrict__ Wr) {
    int warp = (blockIdx.x * blockDim.x + threadIdx.x) >> 5;
    int lane = threadIdx.x & 31;
    if (warp >= SEQ) return;
    const float* xr = x + (size_t)warp * DIM;
    float acc[NE];
    #pragma unroll
    for (int e = 0; e < NE; e++) acc[e] = 0.f;
    for (int d = lane; d < DIM; d += 32) {
        float xv = xr[d];
        #pragma unroll
        for (int e = 0; e < NE; e++) acc[e] += xv * Wr[d * NE + e];
    }
    #pragma unroll
    for (int e = 0; e < NE; e++)
        #pragma unroll
        for (int off = 16; off; off >>= 1)
            acc[e] += __shfl_down_sync(0xffffffffu, acc[e], off);
    if (lane == 0) {
        int i1 = 0;
        #pragma unroll
        for (int e = 1; e < NE; e++) if (acc[e] > acc[i1]) i1 = e;
        int i2 = (i1 == 0) ? 1 : 0;
        #pragma unroll
        for (int e = 0; e < NE; e++) if (e != i1 && acc[e] > acc[i2]) i2 = e;
        float w1 = 1.f / (1.f + expf(acc[i2] - acc[i1]));
        int s0 = atomicAdd(&g_cnt[i1], 1);
        int s1 = atomicAdd(&g_cnt[i2], 1);
        g_eid[warp * 2]  = i1; g_eid[warp * 2 + 1]  = i2;
        g_slot[warp * 2] = s0; g_slot[warp * 2 + 1] = s1;
        g_w[warp * 2]    = w1; g_w[warp * 2 + 1]    = 1.f - w1;
    }
}

__global__ void gather_kernel() {
    int pair = blockIdx.x;
    int n = pair >> 1, j = pair & 1;
    int e = g_eid[n * 2 + j], s = g_slot[n * 2 + j];
    size_t dst = ((size_t)e * CAP + s) * DW;
    size_t src = (size_t)n * DW;
    for (int i = threadIdx.x; i < DW / 4; i += blockDim.x) {
        ((uint4*)(g_xehi + dst))[i] = ((const uint4*)(g_hn2hi + src))[i];
        ((uint4*)(g_xelo + dst))[i] = ((const uint4*)(g_hn2lo + src))[i];
    }
}

__global__ void silu_pack_kernel() {
    int e = blockIdx.z;
    int r = blockIdx.y;
    if (r >= g_cnt[e]) return;
    size_t base = ((size_t)e * CAP + r) * FF;
    size_t wbase = ((size_t)e * CAP + r) * FW;
    int p = blockIdx.x * blockDim.x + threadIdx.x;   // pair index < FW
    float g0 = g_gate[base + 2 * p], u0 = g_up[base + 2 * p];
    float g1 = g_gate[base + 2 * p + 1], u1 = g_up[base + 2 * p + 1];
    float a0 = (g0 / (1.f + expf(-g0))) * u0;
    float a1 = (g1 / (1.f + expf(-g1))) * u1;
    uint32_t h, l;
    hilo(a0, a1, h, l);
    g_acthi[wbase + p] = h;
    g_actlo[wbase + p] = l;
}

__global__ void combine_kernel(float* __restrict__ out) {
    int idx = blockIdx.x * blockDim.x + threadIdx.x;
    if (idx >= SEQ * DIM) return;
    int n = idx >> 11;
    int d = idx & (DIM - 1);
    int e0 = g_eid[n * 2],  e1 = g_eid[n * 2 + 1];
    int s0 = g_slot[n * 2], s1 = g_slot[n * 2 + 1];
    out[idx] = g_h2[idx]
             + g_w[n * 2]     * g_down[((size_t)e0 * CAP + s0) * DIM + d]
             + g_w[n * 2 + 1] * g_down[((size_t)e1 * CAP + s1) * DIM + d];
}

// ---------------- launch -------------------------------------------------------
extern "C" void kernel_launch(void* const* d_in, const int* in_sizes, int n_in,
                              void* d_out, int out_size) {
    const float* hidden = (const float*)d_in[0];
    const int*   pos    = (const int*)  d_in[1];
    const float* ln1    = (const float*)d_in[2];
    const float* Wq     = (const float*)d_in[3];
    const float* Wk     = (const float*)d_in[4];
    const float* Wv     = (const float*)d_in[5];
    const float* Wo     = (const float*)d_in[6];
    const float* ln2    = (const float*)d_in[7];
    const float* Wr     = (const float*)d_in[8];
    const float* W1     = (const float*)d_in[9];
    const float* W3     = (const float*)d_in[10];
    const float* W2     = (const float*)d_in[11];
    float* out = (float*)d_out;

    uint32_t *p_hnhi, *p_hnlo, *p_athi, *p_atlo, *p_hn2hi, *p_hn2lo, *p_xehi, *p_xelo, *p_acthi, *p_actlo;
    float *p_wqkv, *p_qkv, *p_o, *p_h2, *p_hn2, *p_gate, *p_up, *p_down;
    cudaGetSymbolAddress((void**)&p_hnhi, g_hnhi);
    cudaGetSymbolAddress((void**)&p_hnlo, g_hnlo);
    cudaGetSymbolAddress((void**)&p_wqkv, g_wqkv);
    cudaGetSymbolAddress((void**)&p_qkv,  g_qkv);
    cudaGetSymbolAddress((void**)&p_athi, g_athi);
    cudaGetSymbolAddress((void**)&p_atlo, g_atlo);
    cudaGetSymbolAddress((void**)&p_o,    g_o);
    cudaGetSymbolAddress((void**)&p_h2,   g_h2);
    cudaGetSymbolAddress((void**)&p_hn2,  g_hn2);
    cudaGetSymbolAddress((void**)&p_hn2hi, g_hn2hi);
    cudaGetSymbolAddress((void**)&p_hn2lo, g_hn2lo);
    cudaGetSymbolAddress((void**)&p_xehi, g_xehi);
    cudaGetSymbolAddress((void**)&p_xelo, g_xelo);
    cudaGetSymbolAddress((void**)&p_gate, g_gate);
    cudaGetSymbolAddress((void**)&p_up,   g_up);
    cudaGetSymbolAddress((void**)&p_acthi, g_acthi);
    cudaGetSymbolAddress((void**)&p_actlo, g_actlo);
    cudaGetSymbolAddress((void**)&p_down, g_down);
    int* p_cnt;
    cudaGetSymbolAddress((void**)&p_cnt, g_cnt);

    static int smem_set = 0;
    if (!smem_set) {
        cudaFuncSetAttribute(gemm_tc, cudaFuncAttributeMaxDynamicSharedMemorySize, GSMEM_BYTES);
        smem_set = 1;
    }

    zero_cnt_kernel<<<1, 32>>>();
    rmsnorm_pack_kernel<<<SEQ, 256>>>(hidden, ln1, p_hnhi, p_hnlo);
    pack_qkv_kernel<<<(DIM * QKVN + 255) / 256, 256>>>(Wq, Wk, Wv);

    // QKV projection: A packed [2048, 1024w], B fp32 [2048, 3072]
    gemm_tc<<<dim3(QKVN / BN, SEQ / BM, 1), 256, GSMEM_BYTES>>>(
        p_hnhi, p_hnlo, p_wqkv, p_qkv, SEQ, QKVN, DIM, 0, 0, 0, 0);

    rope_kernel<<<(SEQ * NH * (HD / 2) + 255) / 256, 256>>>(p_qkv, pos, NH, QKVN, 0);
    rope_kernel<<<(SEQ * KVH * (HD / 2) + 255) / 256, 256>>>(p_qkv, pos, KVH, QKVN, 2048);

    attn_tc<<<dim3(SEQ / 64, NH, 1), 128>>>(p_qkv, p_athi, p_atlo);

    // O projection + residual
    gemm_tc<<<dim3(DIM / BN, SEQ / BM, 1), 256, GSMEM_BYTES>>>(
        p_athi, p_atlo, Wo, p_o, SEQ, DIM, NH * HD, 0, 0, 0, 0);
    add_kernel<<<(SEQ * DIM + 255) / 256, 256>>>(hidden, p_o, p_h2, SEQ * DIM);

    rmsnorm_both_kernel<<<SEQ, 256>>>(p_h2, ln2, p_hn2, p_hn2hi, p_hn2lo);
    router_kernel<<<(SEQ * 32 + 255) / 256, 256>>>(p_hn2, Wr);
    gather_kernel<<<SEQ * 2, 256>>>();

    // expert GEMMs (device-count early exit); A strides in packed words
    gemm_tc<<<dim3(FF / BN, CAP / BM, NE), 256, GSMEM_BYTES>>>(
        p_xehi, p_xelo, W1, p_gate, CAP, FF, DIM, p_cnt,
        (size_t)CAP * DW, (size_t)DIM * FF, (size_t)CAP * FF);
    gemm_tc<<<dim3(FF / BN, CAP / BM, NE), 256, GSMEM_BYTES>>>(
        p_xehi, p_xelo, W3, p_up, CAP, FF, DIM, p_cnt,
        (size_t)CAP * DW, (size_t)DIM * FF, (size_t)CAP * FF);
    silu_pack_kernel<<<dim3(FW / 256, CAP, NE), 256>>>();
    gemm_tc<<<dim3(DIM / BN, CAP / BM, NE), 256, GSMEM_BYTES>>>(
        p_acthi, p_actlo, W2, p_down, CAP, DIM, FF, p_cnt,
        (size_t)CAP * FW, (size_t)FF * DIM, (size_t)CAP * DIM);

    combine_kernel<<<(SEQ * DIM + 255) / 256, 256>>>(out);
}